// round 8
// baseline (speedup 1.0000x reference)
#include <cuda_runtime.h>

// Problem constants (reference: shape_data=[8,32,32], pow=1, dt=dx=dy=1)
#define NN 1024
#define NT 8
#define NX 32
#define NY 32

__device__ __forceinline__ void stg256(float* p,
                                       float a0, float a1, float a2, float a3,
                                       float a4, float a5, float a6, float a7) {
    asm volatile("st.global.v8.f32 [%0], {%1,%2,%3,%4,%5,%6,%7,%8};"
                 :: "l"(p), "f"(a0), "f"(a1), "f"(a2), "f"(a3),
                    "f"(a4), "f"(a5), "f"(a6), "f"(a7)
                 : "memory");
}

// One CTA per (b, t, j0..j0+3): writes 4 rows of each of D, lower, upper.
// Asymmetric barrier: all warps arrive; only band warps wait. Zero-only warps
// stream their stores immediately, decoupled from staging LDG latency.
// grid: x = j/4 (0..255), y = t (0..7), z = b
__global__ __launch_bounds__(256) void spde_prior_kernel(
    const float* __restrict__ kappa,  // [n_b,1,NN,NT]
    const float* __restrict__ mm,     // [n_b,2,NN,NT]
    const float* __restrict__ HH,     // [n_b,2,2,NN,NT]
    const float* __restrict__ tau,    // [n_b,1,NN,NT]
    float* __restrict__ out)          // [n_b,3,NT,NN,NN]
{
    const int t   = blockIdx.y;
    const int b   = blockIdx.z;
    const int tid = threadIdx.x;
    const int j0  = blockIdx.x << 2;
    const int ii  = j0 >> 5;          // grid row of all 4 j's (4 | 32)
    const int jj0 = j0 & 31;

    // Staged M-entries for 18 nodes (rows ii-1..ii+1, cols jj0-1..jj0+4)
    // at times t (ts=0) and t+1 (ts=1), geometric layout:
    // se[ts][ndi][ndj][a+1][b+1] = M[node, node + (a,b)]
    __shared__ float se[2][3][6][3][3];
    __shared__ float sw[2][3][6];     // w = 1/tau^2 per node

    if (tid < 36) {
        const int ts  = tid >= 18;
        const int idx = tid - ts * 18;
        const int ndi = idx / 6;          // 0..2  -> di = ndi-1
        const int ndj = idx % 6;          // 0..5  -> dj = ndj-1
        const int tt  = t + ts;
        const int ni  = ii + ndi - 1;
        const int nj  = jj0 + ndj - 1;
        const bool v  = (tt < NT) && (ni >= 0) && (ni < NY) && (nj >= 0) && (nj < NX);
        float wq = 0.f, c0 = 0.f, cE = 0.f, cW = 0.f, cN = 0.f, cS = 0.f, cx = 0.f;
        if (v) {
            const int n     = ni * NX + nj;
            const int kbase = (b * NN + n) * NT + tt;
            const float ka  = __ldg(&kappa[kbase]);
            const float ta  = __ldg(&tau[kbase]);
            const float m1  = __ldg(&mm[(b * 2 * NN + n) * NT + tt]);
            const float m2  = __ldg(&mm[((b * 2 + 1) * NN + n) * NT + tt]);
            const float h11 = __ldg(&HH[(b * 4 * NN + n) * NT + tt]);
            const float h12 = __ldg(&HH[((b * 4 + 1) * NN + n) * NT + tt]);
            const float h22 = __ldg(&HH[((b * 4 + 3) * NN + n) * NT + tt]);
            wq = 1.f / (ta * ta);                    // dt/tau^2, dt=1
            c0 = 1.f + ka * ka + 2.f * (h11 + h22);  // M center = 1 + A center
            cE = -h11 + 0.5f * m1;
            cW = -h11 - 0.5f * m1;
            cN = -h22 + 0.5f * m2;
            cS = -h22 - 0.5f * m2;
            cx = 0.5f * h12;
        }
        // geometric entry table: [a+1][b+1], a = di of entry, b = dj
        const float ent[3][3] = { { -cx, cS,  cx },
                                  {  cW, c0,  cE },
                                  {  cx, cN, -cx } };
        #pragma unroll
        for (int a = 0; a < 3; a++)
            #pragma unroll
            for (int bb = 0; bb < 3; bb++) {
                // entry is zero if its COLUMN node is off-grid (Dirichlet)
                const int ci = ni + a - 1, cj = nj + bb - 1;
                const bool cv = v && (ci >= 0) && (ci < NY) && (cj >= 0) && (cj < NX);
                se[ts][ndi][ndj][a][bb] = cv ? ent[a][bb] : 0.f;
            }
        sw[ts][ndi][ndj] = wq;   // 0 for invalid node -> its terms vanish
    }

    const int half = tid >> 7;        // row pair: 0 -> rows {0,1}, 1 -> rows {2,3}
    const int t128 = tid & 127;
    const int c0   = t128 << 3;       // 8-column span base
    const int ki   = c0 >> 5;
    const int kjb  = c0 & 31;         // 0, 8, 16, 24
    const int ddi  = ki - ii;

    // can this thread's 8-col window touch the band of its two rows?
    const bool inband = (ddi >= -2) && (ddi <= 2) &&
                        (kjb <= jj0 + 5) && (kjb + 7 >= jj0 - 2);

    // Asymmetric barrier: staging STS (program-order before this point) is
    // published by bar.arrive; only warps that will READ smem block on bar.sync.
    if (__ballot_sync(0xffffffffu, inband) != 0u) {
        asm volatile("bar.sync 0, 256;" ::: "memory");
    } else {
        asm volatile("bar.arrive 0, 256;" ::: "memory");
    }

    const size_t blk = (size_t)NT * NN * NN;   // block stride in floats
    float* base = out + ((size_t)b * 3 * NT + t) * (size_t)NN * NN
                      + (size_t)j0 * NN + c0;

    #pragma unroll
    for (int r = 0; r < 2; r++) {
        const int jq = half * 2 + r;
        float vD[8] = {0,0,0,0,0,0,0,0};
        float vL[8] = {0,0,0,0,0,0,0,0};
        float vU[8] = {0,0,0,0,0,0,0,0};
        if (inband) {
            const int jj = jj0 + jq;
            #pragma unroll
            for (int c = 0; c < 8; c++) {
                const int ddj = kjb + c - jj;
                if (ddj < -2 || ddj > 2) continue;
                // D[j,k] = sum over neighbors i of j: w_i * M[i,j] * M[i,k]
                float sum = 0.f;
                #pragma unroll
                for (int a = -1; a <= 1; a++)
                    #pragma unroll
                    for (int bo = -1; bo <= 1; bo++) {
                        const int d2i = ddi - a, d2j = ddj - bo;
                        if (d2i < -1 || d2i > 1 || d2j < -1 || d2j > 1) continue;
                        const int sj = jq + bo + 1;   // in [0,5]
                        sum += sw[0][a + 1][sj]
                             * se[0][a + 1][sj][1 - a][1 - bo]      // M[i,j]
                             * se[0][a + 1][sj][d2i + 1][d2j + 1];  // M[i,k]
                    }
                if (ddi == 0 && ddj == 0 && t < NT - 1)
                    sum += sw[1][1][jq + 1];          // + w_{t+1}[j] on diagonal
                vD[c] = sum;

                if (ddi >= -1 && ddi <= 1 && ddj >= -1 && ddj <= 1) {
                    // lower[t][j,k] = -w_t[k] * M_t[k,j]     (t==0 block zero)
                    if (t > 0)
                        vL[c] = -sw[0][ddi + 1][jq + ddj + 1]
                              * se[0][ddi + 1][jq + ddj + 1][1 - ddi][1 - ddj];
                    // upper[t][j,k] = -w_{t+1}[j] * M_{t+1}[j,k]  (t==NT-1 zero)
                    if (t < NT - 1)
                        vU[c] = -sw[1][1][jq + 1]
                              * se[1][1][jq + 1][ddi + 1][ddj + 1];
                }
            }
        }
        float* p = base + (size_t)jq * NN;
        stg256(p,           vD[0], vD[1], vD[2], vD[3], vD[4], vD[5], vD[6], vD[7]);
        stg256(p + blk,     vL[0], vL[1], vL[2], vL[3], vL[4], vL[5], vL[6], vL[7]);
        stg256(p + 2 * blk, vU[0], vU[1], vU[2], vU[3], vU[4], vU[5], vU[6], vU[7]);
    }
}

extern "C" void kernel_launch(void* const* d_in, const int* in_sizes, int n_in,
                              void* d_out, int out_size) {
    const float* kappa = (const float*)d_in[0];
    const float* mm    = (const float*)d_in[1];
    const float* HH    = (const float*)d_in[2];
    const float* tau   = (const float*)d_in[3];
    float* out         = (float*)d_out;

    const int n_b = in_sizes[0] / (NN * NT);   // kappa is [n_b,1,NN,NT]
    dim3 grid(NN / 4, NT, n_b);
    spde_prior_kernel<<<grid, 256>>>(kappa, mm, HH, tau, out);
}

// round 9
// speedup vs baseline: 1.0064x; 1.0064x over previous
#include <cuda_runtime.h>

// Problem constants (reference: shape_data=[8,32,32], pow=1, dt=dx=dy=1)
#define NN 1024
#define NT 8
#define NX 32
#define NY 32

__device__ __forceinline__ void stg256(float* p, const float* a) {
    asm volatile("st.global.v8.f32 [%0], {%1,%2,%3,%4,%5,%6,%7,%8};"
                 :: "l"(p), "f"(a[0]), "f"(a[1]), "f"(a[2]), "f"(a[3]),
                    "f"(a[4]), "f"(a[5]), "f"(a[6]), "f"(a[7])
                 : "memory");
}

// One CTA per (b, t, j0..j0+3): writes 4 rows of each of D, lower, upper.
// 256 threads: tid>>7 selects row pair; tid&127 selects an 8-column span.
// Forced to 32 regs (8 CTAs/SM) to maximize resident store parallelism.
// grid: x = j/4 (0..255), y = t (0..7), z = b
__global__ __launch_bounds__(256, 8) void spde_prior_kernel(
    const float* __restrict__ kappa,  // [n_b,1,NN,NT]
    const float* __restrict__ mm,     // [n_b,2,NN,NT]
    const float* __restrict__ HH,     // [n_b,2,2,NN,NT]
    const float* __restrict__ tau,    // [n_b,1,NN,NT]
    float* __restrict__ out)          // [n_b,3,NT,NN,NN]
{
    const int t   = blockIdx.y;
    const int b   = blockIdx.z;
    const int tid = threadIdx.x;
    const int j0  = blockIdx.x << 2;
    const int ii  = j0 >> 5;          // grid row of all 4 j's (4 | 32)
    const int jj0 = j0 & 31;

    // Staged M-entries for 18 nodes (rows ii-1..ii+1, cols jj0-1..jj0+4)
    // at times t (ts=0) and t+1 (ts=1), geometric layout:
    // se[ts][ndi][ndj][a+1][b+1] = M[node, node + (a,b)]
    __shared__ float se[2][3][6][3][3];
    __shared__ float sw[2][3][6];     // w = 1/tau^2 per node

    if (tid < 36) {
        const int ts  = tid >= 18;
        const int idx = tid - ts * 18;
        const int ndi = idx / 6;          // 0..2  -> di = ndi-1
        const int ndj = idx % 6;          // 0..5  -> dj = ndj-1
        const int tt  = t + ts;
        const int ni  = ii + ndi - 1;
        const int nj  = jj0 + ndj - 1;
        const bool v  = (tt < NT) && (ni >= 0) && (ni < NY) && (nj >= 0) && (nj < NX);
        float wq = 0.f, c0 = 0.f, cE = 0.f, cW = 0.f, cN = 0.f, cS = 0.f, cx = 0.f;
        if (v) {
            const int n     = ni * NX + nj;
            const int kbase = (b * NN + n) * NT + tt;
            const float ka  = __ldg(&kappa[kbase]);
            const float ta  = __ldg(&tau[kbase]);
            const float m1  = __ldg(&mm[(b * 2 * NN + n) * NT + tt]);
            const float m2  = __ldg(&mm[((b * 2 + 1) * NN + n) * NT + tt]);
            const float h11 = __ldg(&HH[(b * 4 * NN + n) * NT + tt]);
            const float h12 = __ldg(&HH[((b * 4 + 1) * NN + n) * NT + tt]);
            const float h22 = __ldg(&HH[((b * 4 + 3) * NN + n) * NT + tt]);
            wq = 1.f / (ta * ta);                    // dt/tau^2, dt=1
            c0 = 1.f + ka * ka + 2.f * (h11 + h22);  // M center = 1 + A center
            cE = -h11 + 0.5f * m1;
            cW = -h11 - 0.5f * m1;
            cN = -h22 + 0.5f * m2;
            cS = -h22 - 0.5f * m2;
            cx = 0.5f * h12;
        }
        // geometric entry table: [a+1][b+1], a = di of entry, b = dj
        const float ent[3][3] = { { -cx, cS,  cx },
                                  {  cW, c0,  cE },
                                  {  cx, cN, -cx } };
        #pragma unroll
        for (int a = 0; a < 3; a++)
            #pragma unroll
            for (int bb = 0; bb < 3; bb++) {
                // entry is zero if its COLUMN node is off-grid (Dirichlet)
                const int ci = ni + a - 1, cj = nj + bb - 1;
                const bool cv = v && (ci >= 0) && (ci < NY) && (cj >= 0) && (cj < NX);
                se[ts][ndi][ndj][a][bb] = cv ? ent[a][bb] : 0.f;
            }
        sw[ts][ndi][ndj] = wq;   // 0 for invalid node -> its terms vanish
    }
    __syncthreads();

    const int half = tid >> 7;        // row pair: 0 -> rows {0,1}, 1 -> rows {2,3}
    const int t128 = tid & 127;
    const int c0   = t128 << 3;       // 8-column span base
    const int ki   = c0 >> 5;
    const int kjb  = c0 & 31;         // 0, 8, 16, 24
    const int ddi  = ki - ii;

    // can this thread's 8-col window touch the band of its two rows?
    const bool inband = (ddi >= -2) && (ddi <= 2) &&
                        (kjb <= jj0 + 5) && (kjb + 7 >= jj0 - 2);

    const size_t blk = (size_t)NT * NN * NN;   // block stride in floats
    float* base = out + ((size_t)b * 3 * NT + t) * (size_t)NN * NN
                      + (size_t)j0 * NN + c0;

    #pragma unroll
    for (int r = 0; r < 2; r++) {
        const int jq = half * 2 + r;
        const int jj = jj0 + jq;
        float* p = base + (size_t)jq * NN;

        // ---- D block row ----
        {
            float v[8] = {0,0,0,0,0,0,0,0};
            if (inband) {
                #pragma unroll
                for (int c = 0; c < 8; c++) {
                    const int ddj = kjb + c - jj;
                    if (ddj < -2 || ddj > 2) continue;
                    float sum = 0.f;
                    #pragma unroll
                    for (int a = -1; a <= 1; a++)
                        #pragma unroll
                        for (int bo = -1; bo <= 1; bo++) {
                            const int d2i = ddi - a, d2j = ddj - bo;
                            if (d2i < -1 || d2i > 1 || d2j < -1 || d2j > 1) continue;
                            const int sj = jq + bo + 1;   // in [0,5]
                            sum += sw[0][a + 1][sj]
                                 * se[0][a + 1][sj][1 - a][1 - bo]      // M[i,j]
                                 * se[0][a + 1][sj][d2i + 1][d2j + 1];  // M[i,k]
                        }
                    if (ddi == 0 && ddj == 0 && t < NT - 1)
                        sum += sw[1][1][jq + 1];      // + w_{t+1}[j] on diagonal
                    v[c] = sum;
                }
            }
            stg256(p, v);
        }

        // ---- lower block row: -w_t[k] * M_t[k,j]  (t==0 block zero) ----
        {
            float v[8] = {0,0,0,0,0,0,0,0};
            if (inband && t > 0 && ddi >= -1 && ddi <= 1) {
                #pragma unroll
                for (int c = 0; c < 8; c++) {
                    const int ddj = kjb + c - jj;
                    if (ddj < -1 || ddj > 1) continue;
                    v[c] = -sw[0][ddi + 1][jq + ddj + 1]
                         * se[0][ddi + 1][jq + ddj + 1][1 - ddi][1 - ddj];
                }
            }
            stg256(p + blk, v);
        }

        // ---- upper block row: -w_{t+1}[j] * M_{t+1}[j,k]  (t==NT-1 zero) ----
        {
            float v[8] = {0,0,0,0,0,0,0,0};
            if (inband && t < NT - 1 && ddi >= -1 && ddi <= 1) {
                #pragma unroll
                for (int c = 0; c < 8; c++) {
                    const int ddj = kjb + c - jj;
                    if (ddj < -1 || ddj > 1) continue;
                    v[c] = -sw[1][1][jq + 1]
                         * se[1][1][jq + 1][ddi + 1][ddj + 1];
                }
            }
            stg256(p + 2 * blk, v);
        }
    }
}

extern "C" void kernel_launch(void* const* d_in, const int* in_sizes, int n_in,
                              void* d_out, int out_size) {
    const float* kappa = (const float*)d_in[0];
    const float* mm    = (const float*)d_in[1];
    const float* HH    = (const float*)d_in[2];
    const float* tau   = (const float*)d_in[3];
    float* out         = (float*)d_out;

    const int n_b = in_sizes[0] / (NN * NT);   // kappa is [n_b,1,NN,NT]
    dim3 grid(NN / 4, NT, n_b);
    spde_prior_kernel<<<grid, 256>>>(kappa, mm, HH, tau, out);
}